// round 2
// baseline (speedup 1.0000x reference)
#include <cuda_runtime.h>
#include <cuda_bf16.h>

// ROI mean-pool, v2: column-prefix-only formulation.
//
// fmap:  [B=64, C=256, H=80, W=80] float32
// boxes: [B=64, N=100, 4] xyxy in [0,640]
// out:   [B, N, C] float32
//
// One CTA per (b,c) plane (grid=16384).
// Phase 1: thread x accumulates column prefix C[y][x] = sum_{y'<y} f[y'][x]
//          directly from coalesced global loads (no stage-in, no row scan).
// Phase 2: box sum = sum_{x=x1}^{x2-1} (C[y2][x] - C[y1][x]).
// SMEM traffic per CTA: ~6.5K STS + ~5.4K LDS (vs 32.4K word-ops in v1).

#define Bn   64
#define Cn   256
#define Hn   80
#define Wn   80
#define Nn   100

__global__ __launch_bounds__(256, 1)
void roi_colprefix_pool_kernel(const float* __restrict__ fmap,
                               const float* __restrict__ boxes,
                               float* __restrict__ out)
{
    // C[y][x] for y in 0..80 (row 0 is the zero border), x in 0..79.
    __shared__ float S[(Hn + 1) * Wn];   // 81*80*4 = 25,920 B

    const int p   = blockIdx.x;          // plane id = b*Cn + c
    const int b   = p >> 8;
    const int c   = p & 255;
    const int tid = threadIdx.x;

    const float* __restrict__ plane = fmap + (size_t)p * (Hn * Wn);

    // Phase 1: fused load + column inclusive scan.
    // Threads 0..79 each own one column. Global loads are coalesced
    // (at iteration y, lanes read consecutive addresses). Loads are
    // independent of the FADD carry chain, so they pipeline freely.
    if (tid < Wn) {
        S[tid] = 0.0f;                   // zero border row
        float acc = 0.0f;
        #pragma unroll 8
        for (int y = 0; y < Hn; ++y) {
            acc += plane[y * Wn + tid];
            S[(y + 1) * Wn + tid] = acc; // coalesced, conflict-free STS
        }
    }
    __syncthreads();

    // Phase 2: one thread per box (threads 0..99).
    const float* __restrict__ bx = boxes + (size_t)b * (Nn * 4);
    float* __restrict__ ob = out + (size_t)b * (Nn * Cn) + c;

    if (tid < Nn) {
        float4 bb = reinterpret_cast<const float4*>(bx)[tid];
        // Match JAX exactly: IEEE div by 640, IEEE mul by 80, trunc, clip.
        int x1 = min(max((int)(__fmul_rn(__fdiv_rn(bb.x, 640.0f), 80.0f)), 0), Wn);
        int y1 = min(max((int)(__fmul_rn(__fdiv_rn(bb.y, 640.0f), 80.0f)), 0), Hn);
        int x2 = min(max((int)(__fmul_rn(__fdiv_rn(bb.z, 640.0f), 80.0f)), 0), Wn);
        int y2 = min(max((int)(__fmul_rn(__fdiv_rn(bb.w, 640.0f), 80.0f)), 0), Hn);

        const float* __restrict__ r2 = &S[y2 * Wn];
        const float* __restrict__ r1 = &S[y1 * Wn];

        float s = 0.0f;
        #pragma unroll 4
        for (int x = x1; x < x2; ++x)
            s += r2[x] - r1[x];          // independent LDS pairs, pipelined

        int dy = y2 - y1;
        int dx = x2 - x1;
        bool valid = (dy > 0) && (dx > 0);
        int  area  = max(dy * dx, 1);

        ob[(size_t)tid * Cn] = valid ? s / (float)area : 0.0f;
    }
}

extern "C" void kernel_launch(void* const* d_in, const int* in_sizes, int n_in,
                              void* d_out, int out_size)
{
    const float* fmap  = (const float*)d_in[0];   // [64,256,80,80]
    const float* boxes = (const float*)d_in[1];   // [64,100,4]
    float*       out   = (float*)d_out;           // [64,100,256]

    (void)in_sizes; (void)n_in; (void)out_size;

    roi_colprefix_pool_kernel<<<Bn * Cn, 256>>>(fmap, boxes, out);
}

// round 3
// speedup vs baseline: 1.1370x; 1.1370x over previous
#include <cuda_runtime.h>
#include <cuda_bf16.h>

// ROI mean-pool, v3: float4 all-thread stage-in + in-place column scan +
// column-prefix box evaluation.
//
// fmap:  [B=64, C=256, H=80, W=80] float32
// boxes: [B=64, N=100, 4] xyxy in [0,640]
// out:   [B, N, C] float32
//
// One CTA per (b,c) plane (grid=16384, 8 CTAs/SM at 25.9KB smem).
// Phase 1: 256 threads, LDG.128 coalesced stream of the 25.6KB plane (high MLP).
// Phase 2: 80 threads do in-place inclusive column scan (S becomes C[1..80]).
// Phase 3: box sum = sum_x (C[y2][x] - C[y1][x]); y==0 uses a zero row.

#define Bn   64
#define Cn   256
#define Hn   80
#define Wn   80
#define Nn   100

__global__ __launch_bounds__(256, 1)
void roi_pool_v3_kernel(const float* __restrict__ fmap,
                        const float* __restrict__ boxes,
                        float* __restrict__ out)
{
    // [0 .. 6399]   : plane, then (in-place) inclusive column prefix rows 1..80
    // [6400 .. 6479]: zero row (acts as C[0])
    __shared__ float S[Hn * Wn + Wn];    // 6480 floats = 25,920 B

    const int p   = blockIdx.x;          // plane id = b*Cn + c
    const int b   = p >> 8;
    const int c   = p & 255;
    const int tid = threadIdx.x;

    const float* __restrict__ plane = fmap + (size_t)p * (Hn * Wn);

    // Phase 1: coalesced float4 stage-in using ALL 256 threads.
    // 1600 float4; each thread has 6-7 independent LDG.128 in flight.
    #pragma unroll
    for (int i = tid; i < (Hn * Wn) / 4; i += 256) {
        float4 v = reinterpret_cast<const float4*>(plane)[i];
        reinterpret_cast<float4*>(S)[i] = v;
    }
    if (tid < Wn) S[Hn * Wn + tid] = 0.0f;   // zero border row
    __syncthreads();

    // Phase 2: in-place inclusive column scan. Thread x owns column x.
    // At each y, the 80 active lanes hit 80 consecutive words: conflict-free.
    // Carry chain = 80 FADDs; LDS addresses are static so loads pipeline ahead.
    if (tid < Wn) {
        float acc = 0.0f;
        #pragma unroll 8
        for (int y = 0; y < Hn; ++y) {
            acc += S[y * Wn + tid];
            S[y * Wn + tid] = acc;       // S[y*Wn+x] = C[y+1][x]
        }
    }
    __syncthreads();

    // Phase 3: one thread per box.
    const float* __restrict__ bx = boxes + (size_t)b * (Nn * 4);
    float* __restrict__ ob = out + (size_t)b * (Nn * Cn) + c;

    if (tid < Nn) {
        float4 bb = reinterpret_cast<const float4*>(bx)[tid];
        // Match JAX exactly: IEEE div by 640, IEEE mul by 80, trunc, clip.
        int x1 = min(max((int)(__fmul_rn(__fdiv_rn(bb.x, 640.0f), 80.0f)), 0), Wn);
        int y1 = min(max((int)(__fmul_rn(__fdiv_rn(bb.y, 640.0f), 80.0f)), 0), Hn);
        int x2 = min(max((int)(__fmul_rn(__fdiv_rn(bb.z, 640.0f), 80.0f)), 0), Wn);
        int y2 = min(max((int)(__fmul_rn(__fdiv_rn(bb.w, 640.0f), 80.0f)), 0), Hn);

        // C[y] lives at S[(y-1)*Wn]; C[0] is the zero row at S[Hn*Wn].
        const float* __restrict__ r2 = (y2 > 0) ? &S[(y2 - 1) * Wn] : &S[Hn * Wn];
        const float* __restrict__ r1 = (y1 > 0) ? &S[(y1 - 1) * Wn] : &S[Hn * Wn];

        float s = 0.0f;
        #pragma unroll 4
        for (int x = x1; x < x2; ++x)
            s += r2[x] - r1[x];          // independent LDS pairs, pipelined

        int dy = y2 - y1;
        int dx = x2 - x1;
        bool valid = (dy > 0) && (dx > 0);
        int  area  = max(dy * dx, 1);

        ob[(size_t)tid * Cn] = valid ? s / (float)area : 0.0f;
    }
}

extern "C" void kernel_launch(void* const* d_in, const int* in_sizes, int n_in,
                              void* d_out, int out_size)
{
    const float* fmap  = (const float*)d_in[0];   // [64,256,80,80]
    const float* boxes = (const float*)d_in[1];   // [64,100,4]
    float*       out   = (float*)d_out;           // [64,100,256]

    (void)in_sizes; (void)n_in; (void)out_size;

    roi_pool_v3_kernel<<<Bn * Cn, 256>>>(fmap, boxes, out);
}